// round 17
// baseline (speedup 1.0000x reference)
#include <cuda_runtime.h>
#include <math.h>
#include <float.h>
#include <stdint.h>

// Shapes (fixed): z_e [32,64,64,64] f32, emb [512,64] f32.
#define N_TOK    131072
#define HW       4096
#define OFF_SCAL 8388608
#define OFF_IDX  8388613

// Scratch (static device globals: allocation-free).
__device__ float        g_bnorm[512];
__device__ unsigned int g_counts[512];
__device__ double       g_dsum;
__device__ int          g_done;

typedef unsigned long long ull;

// ---- packed f32x2 helpers (Blackwell packed fp32 pipe) ----
__device__ __forceinline__ ull fma2(ull a, ull b, ull c) {
    ull d;
    asm("fma.rn.f32x2 %0, %1, %2, %3;" : "=l"(d) : "l"(a), "l"(b), "l"(c));
    return d;
}
__device__ __forceinline__ ull add2(ull a, ull b) {
    ull d;
    asm("add.rn.f32x2 %0, %1, %2;" : "=l"(d) : "l"(a), "l"(b));
    return d;
}
__device__ __forceinline__ ull pack2(float lo, float hi) {
    ull d;
    asm("mov.b64 %0, {%1, %2};" : "=l"(d) : "f"(lo), "f"(hi));
    return d;
}
__device__ __forceinline__ float lanesum(ull s) {
    float lo, hi;
    asm("mov.b64 {%0, %1}, %2;" : "=f"(lo), "=f"(hi) : "l"(s));
    return lo + hi;
}

// ---- prep: code norms + zero accumulators ----
__global__ void vq_prep(const float* __restrict__ emb) {
    int k = blockIdx.x * 256 + threadIdx.x;     // 0..511
    const float* e = emb + k * 64;
    float s = 0.f;
#pragma unroll
    for (int d = 0; d < 64; ++d) s = fmaf(e[d], e[d], s);
    g_bnorm[k]  = s;
    g_counts[k] = 0u;
    if (k == 0) { g_dsum = 0.0; g_done = 0; }
}

// ---- main: persistent CTAs, 512 threads (4 warps/SMSP for latency hiding).
//      Per tile (64 tokens): 1 token/thread, 8-way code split (64 codes each),
//      proven single-code k-loop; fused z_q scatter; in-kernel finalize. ----
// smem: s_emb f32[32768] | s_bn f32[512] | s_hist u32[512] | s_md f32[512] | s_mi i32[512]
#define SM_FLOATS 34816
#define SM_BYTES  (SM_FLOATS * 4)     // 139264

__global__ __launch_bounds__(512, 1)
void vq_main(const float* __restrict__ z_e, const float* __restrict__ emb,
             float* __restrict__ out) {
    extern __shared__ __align__(16) float sm[];
    float*        s_emb  = sm;                          // 32768 f32 (raw emb rows)
    float*        s_bn   = sm + 32768;                  // 512
    unsigned int* s_hist = (unsigned int*)(sm + 33280); // 512
    float*        s_md   = sm + 33792;                  // 512
    int*          s_mi   = (int*)(sm + 34304);          // 512
    const int tid = threadIdx.x;

    for (int i = tid; i < 8192; i += 512)
        ((float4*)s_emb)[i] = ((const float4*)emb)[i];
    {
        s_bn[tid]   = g_bnorm[tid];
        s_hist[tid] = 0u;
    }
    __syncthreads();

    const int quad  = tid >> 6;          // code octant: codes [quad*64, +64)
    const int tp    = tid & 63;          // token slot within tile
    const int kbase = quad * 64;

    for (int tile = (int)blockIdx.x; tile < 2048; tile += 148) {
        const int n0   = tile * 64;
        const int b    = n0 >> 12;
        const int hw0  = n0 & (HW - 1);
        const float* zp = z_e + ((size_t)b << 18) + hw0 + tp;

        // load token, pack consecutive-d pairs into f32x2 lanes, compute ||z||^2
        ull z0[32];
        float a00 = 0.f, a01 = 0.f;
#pragma unroll
        for (int j = 0; j < 32; j += 2) {
            float u0 = zp[(size_t)(2 * j + 0) << 12];
            float u1 = zp[(size_t)(2 * j + 1) << 12];
            float u2 = zp[(size_t)(2 * j + 2) << 12];
            float u3 = zp[(size_t)(2 * j + 3) << 12];
            a00 = fmaf(u0, u0, a00); a00 = fmaf(u1, u1, a00);
            a01 = fmaf(u2, u2, a01); a01 = fmaf(u3, u3, a01);
            z0[j]     = pack2(u0, u1);
            z0[j + 1] = pack2(u2, u3);
        }
        const float A0 = a00 + a01;

        float dmin0 = FLT_MAX;
        int   imin0 = 0;
#pragma unroll 1
        for (int k = kbase; k < kbase + 64; ++k) {
            const ulonglong2* row = (const ulonglong2*)(s_emb + (k << 6));
            ull c00 = 0ull, c01 = 0ull;
#pragma unroll
            for (int j = 0; j < 16; j += 2) {
                ulonglong2 q0 = row[j];
                ulonglong2 q1 = row[j + 1];
                c00 = fma2(z0[2 * j + 0], q0.x, c00);
                c01 = fma2(z0[2 * j + 1], q0.y, c01);
                c00 = fma2(z0[2 * j + 2], q1.x, c00);
                c01 = fma2(z0[2 * j + 3], q1.y, c01);
            }
            float bnk  = s_bn[k];
            float dot0 = lanesum(add2(c00, c01));
            // replicate reference rounding: d = fl( fl(A + B) - 2*dot )
            float d0 = fmaf(dot0, -2.f, A0 + bnk);
            if (d0 < dmin0) { dmin0 = d0; imin0 = k; }
        }

        // publish per-octant candidates
        s_md[quad * 64 + tp] = dmin0;
        s_mi[quad * 64 + tp] = imin0;
        __syncthreads();

        // merge across octants (ascending quad = ascending code: strict < keeps
        // the lowest index on exact ties, matching the reference argmin)
        if (tid < 64) {
            float d = s_md[tid];
            int   i = s_mi[tid];
#pragma unroll
            for (int q = 1; q < 8; ++q) {
                float dq = s_md[q * 64 + tid];
                int   iq = s_mi[q * 64 + tid];
                if (dq < d) { d = dq; i = iq; }
            }
            int n = n0 + tid;
            out[OFF_IDX + n] = (float)i;
            s_mi[tid]        = i;            // final index for the scatter phase
            atomicAdd(&s_hist[i], 1u);
            float v = d;
#pragma unroll
            for (int o = 16; o; o >>= 1) v += __shfl_xor_sync(0xffffffffu, v, o);
            if ((tid & 31) == 0) atomicAdd(&g_dsum, (double)v);
        }
        __syncthreads();

        // fused z_q scatter: 256 items (16 token-groups x 16 d4), tid<256 one each.
        if (tid < 256) {
            int d4 = tid >> 4;                // 0..15
            int t4 = (tid & 15) << 2;         // token group base 0..60
            const int4 ix = *(const int4*)(s_mi + t4);
            float4 e0 = *(const float4*)(emb + ix.x * 64 + d4 * 4);
            float4 e1 = *(const float4*)(emb + ix.y * 64 + d4 * 4);
            float4 e2 = *(const float4*)(emb + ix.z * 64 + d4 * 4);
            float4 e3 = *(const float4*)(emb + ix.w * 64 + d4 * 4);
            int base = (b << 18) + (d4 << 14) + hw0 + t4;
            *(float4*)(out + base         ) = make_float4(e0.x, e1.x, e2.x, e3.x);
            *(float4*)(out + base +  4096 ) = make_float4(e0.y, e1.y, e2.y, e3.y);
            *(float4*)(out + base +  8192 ) = make_float4(e0.z, e1.z, e2.z, e3.z);
            *(float4*)(out + base + 12288 ) = make_float4(e0.w, e1.w, e2.w, e3.w);
        }
        __syncthreads();   // protect s_md/s_mi/s_hist for the next tile
    }

    // flush per-CTA histogram once
    {
        unsigned int c = s_hist[tid];
        if (c) atomicAdd(&g_counts[tid], c);
    }
    __threadfence();
    __syncthreads();

    // ticket: the last CTA to finish runs the scalar finalize in-kernel
    if (tid == 0) s_hist[0] = (atomicAdd(&g_done, 1) == 147) ? 1u : 0u;
    __syncthreads();
    if (s_hist[0]) {
        __threadfence();
        float e = 0.f; int u = 0;
        {
            unsigned int c = g_counts[tid];
            float p = (float)c * (1.0f / 131072.0f);
            if (c > 0) { e = -p * logf(p); u = 1; }
        }
#pragma unroll
        for (int o = 16; o; o >>= 1) {
            e += __shfl_xor_sync(0xffffffffu, e, o);
            u += __shfl_xor_sync(0xffffffffu, u, o);
        }
        if ((tid & 31) == 0) { s_md[tid >> 5] = e; s_mi[64 + (tid >> 5)] = u; }
        __syncthreads();
        if (tid == 0) {
            float ent = 0.f; int used = 0;
            for (int i = 0; i < 16; ++i) { ent += s_md[i]; used += s_mi[64 + i]; }
            float avg = (float)(g_dsum * (1.0 / 131072.0));
            out[OFF_SCAL + 0] = 1.25f * avg;                // loss_vq
            out[OFF_SCAL + 1] = expf(ent);                  // perplexity
            out[OFF_SCAL + 2] = (float)used;                // codes_used
            out[OFF_SCAL + 3] = (float)used / 512.0f;       // usage_ratio
            out[OFF_SCAL + 4] = avg;                        // avg_dist2
            g_done = 0;                                     // replay-safe reset
        }
    }
}

extern "C" void kernel_launch(void* const* d_in, const int* in_sizes, int n_in,
                              void* d_out, int out_size) {
    const float* z_e = (const float*)d_in[0];
    const float* emb = (const float*)d_in[1];
    float*       out = (float*)d_out;

    cudaFuncSetAttribute(vq_main, cudaFuncAttributeMaxDynamicSharedMemorySize,
                         SM_BYTES);

    vq_prep<<<2, 256>>>(emb);
    vq_main<<<148, 512, SM_BYTES>>>(z_e, emb, out);
}